// round 1
// baseline (speedup 1.0000x reference)
#include <cuda_runtime.h>
#include <cstdint>

#define NN 20000
#define NE 320000
#define BFDIM 128
#define FD 64
#define RD 32
#define KSEL 160000
#define NITER 4

typedef unsigned long long ull;

// ---------------- scratch (device globals; no allocation allowed) ----------------
__device__ __align__(16) float g_rel[RD * BFDIM];      // relation messages (iter-invariant)
__device__ float g_wa[4 * BFDIM];                      // W @ a[i]
__device__ float g_drel[4 * RD];                       // rel · wa per relation
__device__ float g_wsumT[FD * FD];                     // (lw1+lw2) transposed [j][f]
__device__ float g_w2T[FD * FD];                       // lw2 transposed [j][f]
__device__ float g_tr[BFDIM];                          // readout @ tr_w.T + tr_b (per iter)
__device__ float g_rsum[BFDIM];                        // sum over nodes of x (per iter)
__device__ float g_nx[NN];
__device__ unsigned g_m[NN];                           // sortable-uint segment max
__device__ float g_denom[NN];
__device__ float g_araw[NE];
__device__ float g_ex[NE];
__device__ float g_aN[NE];
__device__ __align__(16) float g_scat[NN * BFDIM];
__device__ unsigned g_hist[65536];
__device__ ull g_prefix;
__device__ long long g_remaining;
__device__ ull g_thresh;

// ---------------- helpers ----------------
__device__ __forceinline__ unsigned f2sort(float f) {
    unsigned u = __float_as_uint(f);
    return u ^ ((u & 0x80000000u) ? 0xFFFFFFFFu : 0x80000000u);
}
__device__ __forceinline__ float sort2f(unsigned u) {
    unsigned b = u ^ ((u & 0x80000000u) ? 0x80000000u : 0xFFFFFFFFu);
    return __uint_as_float(b);
}

// ---------------- per-iter zero ----------------
__global__ void k_zero() {
    int i = blockIdx.x * blockDim.x + threadIdx.x;
    if (i < NN * BFDIM) g_scat[i] = 0.f;
    if (i < NN) { g_m[i] = 0u; g_denom[i] = 0.f; }
    if (i < 65536) g_hist[i] = 0u;
    if (i < BFDIM) g_rsum[i] = 0.f;
}

// ---------------- prep (once per launch) ----------------
__global__ void k_prep_rel(const float* __restrict__ q, const float* __restrict__ rw,
                           const float* __restrict__ rb) {
    int t = blockIdx.x * blockDim.x + threadIdx.x;
    if (t >= 2 * 2048) return;
    int b = t >> 11, j = t & 2047;
    const float* qr = q + b * FD;
    const float* wr = rw + j * FD;
    float s = rb[j];
#pragma unroll 16
    for (int k = 0; k < FD; k++) s += qr[k] * wr[k];
    g_rel[t] = s;   // flat [B, R*F] layout == reshape(R,B,F) linear layout
}

__global__ void k_prep_wa(const float* __restrict__ Wm, const float* __restrict__ av) {
    int t = blockIdx.x * blockDim.x + threadIdx.x;
    if (t >= 4 * BFDIM) return;
    int i = t >> 7, j = t & 127;
    float s = 0.f;
#pragma unroll 16
    for (int f = 0; f < FD; f++) s += Wm[j * FD + f] * av[i * FD + f];
    g_wa[t] = s;
}

__global__ void k_prep_drel() {
    int t = blockIdx.x * blockDim.x + threadIdx.x;
    if (t >= 4 * RD) return;
    int i = t >> 5, r = t & 31;
    float s = 0.f;
#pragma unroll 16
    for (int j = 0; j < BFDIM; j++) s += g_rel[r * BFDIM + j] * g_wa[i * BFDIM + j];
    g_drel[t] = s;
}

__global__ void k_prep_w(const float* __restrict__ lw) {
    int t = blockIdx.x * blockDim.x + threadIdx.x;
    if (t >= FD * FD) return;
    int j = t >> 6, f = t & 63;
    float w2 = lw[f * 2 * FD + FD + j];
    g_w2T[j * FD + f] = w2;
    g_wsumT[j * FD + f] = lw[f * 2 * FD + j] + w2;
}

// ---------------- per-node scores + readout partial sums ----------------
__global__ __launch_bounds__(256) void k_nx(const float* __restrict__ x, int it) {
    __shared__ float racc[BFDIM];
    int tid = threadIdx.x;
    if (tid < BFDIM) racc[tid] = 0.f;
    __syncthreads();
    int warp = (blockIdx.x * blockDim.x + tid) >> 5;
    int l = tid & 31;
    const float* wa = g_wa + it * BFDIM;
    if (warp < NN) {
        const float* xr = x + (size_t)warp * BFDIM;
        float x0 = xr[l], x1 = xr[32 + l], x2 = xr[64 + l], x3 = xr[96 + l];
        float v = x0 * wa[l] + x1 * wa[32 + l] + x2 * wa[64 + l] + x3 * wa[96 + l];
#pragma unroll
        for (int o = 16; o; o >>= 1) v += __shfl_xor_sync(0xffffffffu, v, o);
        if (l == 0) g_nx[warp] = v;
        atomicAdd(&racc[l], x0);
        atomicAdd(&racc[32 + l], x1);
        atomicAdd(&racc[64 + l], x2);
        atomicAdd(&racc[96 + l], x3);
    }
    __syncthreads();
    if (tid < BFDIM) atomicAdd(&g_rsum[tid], racc[tid]);
}

// ---------------- trans-readout vector ----------------
__global__ void k_tr(const float* __restrict__ trw, const float* __restrict__ trb) {
    int t = threadIdx.x;
    if (t >= BFDIM) return;
    int b = t >> 6, f = t & 63;
    const float* r = g_rsum + b * FD;
    float s = trb[f];
    const float inv = 1.f / (float)NN;
#pragma unroll 16
    for (int j = 0; j < FD; j++) s += (r[j] * inv) * trw[f * FD + j];
    g_tr[t] = s;
}

// ---------------- edge alpha raw + segment max ----------------
__global__ __launch_bounds__(256) void k_alpha(const int* __restrict__ ei,
                                               const int* __restrict__ ri, int it) {
    int e = blockIdx.x * blockDim.x + threadIdx.x;
    if (e >= NE) return;
    int s = ei[e];
    int r = ri[e];
    float t = g_nx[s] + g_drel[it * RD + r];
    t = t > 0.f ? t : 0.2f * t;
    g_araw[e] = t;
    atomicMax(&g_m[s], f2sort(t));
}

// ---------------- exp + segment sum ----------------
__global__ __launch_bounds__(256) void k_exp(const int* __restrict__ ei) {
    int e = blockIdx.x * blockDim.x + threadIdx.x;
    if (e >= NE) return;
    int s = ei[e];
    float m = sort2f(g_m[s]);
    float ex = expf(g_araw[e] - m);
    g_ex[e] = ex;
    atomicAdd(&g_denom[s], ex);
}

// ---------------- normalize ----------------
__global__ __launch_bounds__(256) void k_norm(const int* __restrict__ ei) {
    int e = blockIdx.x * blockDim.x + threadIdx.x;
    if (e >= NE) return;
    g_aN[e] = g_ex[e] / (g_denom[ei[e]] + 1e-16f);
}

// ---------------- radix select (k-th largest 64-bit key), 16-bit digits ----------------
__device__ __forceinline__ ull edge_key(int e) {
    return ((ull)__float_as_uint(g_aN[e]) << 32) | (unsigned)(0xFFFFFFFFu - (unsigned)e);
}

__global__ __launch_bounds__(256) void k_hist(int shift, int first) {
    int e = blockIdx.x * blockDim.x + threadIdx.x;
    if (e >= NE) return;
    ull key = edge_key(e);
    bool ok = first || ((key >> (shift + 16)) == (g_prefix >> (shift + 16)));
    if (ok) atomicAdd(&g_hist[(unsigned)(key >> shift) & 0xFFFFu], 1u);
}

__global__ __launch_bounds__(1024) void k_pick(int shift, int first) {
    __shared__ unsigned ssum[1024];
    int t = threadIdx.x;
    int base = 65535 - t * 64;  // highest digit of this thread's descending chunk
    unsigned cs = 0;
#pragma unroll 8
    for (int u = 0; u < 64; ++u) cs += g_hist[base - u];
    ssum[t] = cs;
    __syncthreads();
    // inclusive scan over chunks (chunk 0 = highest digits)
    for (int off = 1; off < 1024; off <<= 1) {
        unsigned v = (t >= off) ? ssum[t - off] : 0u;
        __syncthreads();
        ssum[t] += v;
        __syncthreads();
    }
    long long R = first ? (long long)KSEL : g_remaining;
    ull pre = first ? 0ull : g_prefix;
    long long incl = (long long)ssum[t];
    long long cumBefore = incl - (long long)cs;
    if (cumBefore < R && R <= incl) {
        long long cum = cumBefore;
        for (int u = 0; u < 64; ++u) {
            int d = base - u;
            unsigned h = g_hist[d];
            cum += h;
            if (cum >= R) {
                ull np = pre | ((ull)d << shift);
                g_prefix = np;
                g_remaining = R - (cum - h);
                if (shift == 0) g_thresh = np;
                break;
            }
        }
    }
    // clear bins for next level / next iteration
    for (int u = 0; u < 64; ++u) g_hist[base - u] = 0u;
}

// ---------------- masked weighted scatter (warp per edge) ----------------
__global__ __launch_bounds__(256) void k_scatter(const float* __restrict__ x,
                                                 const int* __restrict__ ei,
                                                 const int* __restrict__ ri) {
    int warp = (blockIdx.x * blockDim.x + threadIdx.x) >> 5;
    int l = threadIdx.x & 31;
    if (warp >= NE) return;
    float w = g_aN[warp];
    ull key = ((ull)__float_as_uint(w) << 32) | (unsigned)(0xFFFFFFFFu - (unsigned)warp);
    if (key < g_thresh) return;
    int s = ei[warp], d = ei[NE + warp], r = ri[warp];
    float4 xv = reinterpret_cast<const float4*>(x)[(size_t)s * 32 + l];
    float4 rv = reinterpret_cast<const float4*>(g_rel)[r * 32 + l];
    float a0 = w * (xv.x + rv.x);
    float a1 = w * (xv.y + rv.y);
    float a2 = w * (xv.z + rv.z);
    float a3 = w * (xv.w + rv.w);
    float* p = g_scat + (size_t)d * BFDIM + l * 4;
    asm volatile("red.global.add.v4.f32 [%0], {%1,%2,%3,%4};"
                 :: "l"(p), "f"(a0), "f"(a1), "f"(a2), "f"(a3) : "memory");
}

// ---------------- fused layer linear + broadcast + LN + ELU + residual ----------------
__global__ __launch_bounds__(128) void k_epi(float* __restrict__ x,
                                             const float* __restrict__ lb,
                                             const float* __restrict__ lng,
                                             const float* __restrict__ lnb) {
    __shared__ float sWs[FD * FD];
    __shared__ float sW2[FD * FD];
    __shared__ float sTr[BFDIM];
    __shared__ float sLb[FD], sG[FD], sB[FD];
    __shared__ float4 sX[8][32];
    __shared__ float4 sS[8][32];
    int tid = threadIdx.x;
    for (int i = tid; i < FD * FD; i += 128) { sWs[i] = g_wsumT[i]; sW2[i] = g_w2T[i]; }
    if (tid < BFDIM) sTr[tid] = g_tr[tid];
    if (tid < FD) { sLb[tid] = lb[tid]; sG[tid] = lng[tid]; sB[tid] = lnb[tid]; }
    __syncthreads();
    int w = tid >> 5, l = tid & 31;
    int nbase = blockIdx.x * 8 + w * 2;
    int row0 = w * 2, row1 = w * 2 + 1;
#pragma unroll
    for (int nd = 0; nd < 2; ++nd) {
        int n = nbase + nd;
        sX[row0 + nd][l] = reinterpret_cast<const float4*>(x)[(size_t)n * 32 + l];
        sS[row0 + nd][l] = reinterpret_cast<const float4*>(g_scat)[(size_t)n * 32 + l];
    }
    __syncwarp();

    float acc[2][2][2] = {};
    for (int jv = 0; jv < 16; ++jv) {
        float4 X0a = sX[row0][jv], X1a = sX[row0][16 + jv];
        float4 S0a = sS[row0][jv], S1a = sS[row0][16 + jv];
        float4 X0b = sX[row1][jv], X1b = sX[row1][16 + jv];
        float4 S0b = sS[row1][jv], S1b = sS[row1][16 + jv];
        const float* x0a = (const float*)&X0a; const float* x1a = (const float*)&X1a;
        const float* s0a = (const float*)&S0a; const float* s1a = (const float*)&S1a;
        const float* x0b = (const float*)&X0b; const float* x1b = (const float*)&X1b;
        const float* s0b = (const float*)&S0b; const float* s1b = (const float*)&S1b;
#pragma unroll
        for (int u = 0; u < 4; ++u) {
            int j = jv * 4 + u;
            float wA0 = sWs[j * FD + l], wA1 = sWs[j * FD + 32 + l];
            float wB0 = sW2[j * FD + l], wB1 = sW2[j * FD + 32 + l];
            acc[0][0][0] += x0a[u] * wA0 + s0a[u] * wB0;
            acc[0][0][1] += x0a[u] * wA1 + s0a[u] * wB1;
            acc[0][1][0] += x1a[u] * wA0 + s1a[u] * wB0;
            acc[0][1][1] += x1a[u] * wA1 + s1a[u] * wB1;
            acc[1][0][0] += x0b[u] * wA0 + s0b[u] * wB0;
            acc[1][0][1] += x0b[u] * wA1 + s0b[u] * wB1;
            acc[1][1][0] += x1b[u] * wA0 + s1b[u] * wB0;
            acc[1][1][1] += x1b[u] * wA1 + s1b[u] * wB1;
        }
    }

    const float* sXf = (const float*)sX;
#pragma unroll
    for (int nd = 0; nd < 2; ++nd) {
        int n = nbase + nd;
        int row = row0 + nd;
#pragma unroll
        for (int b = 0; b < 2; ++b) {
            float v0 = acc[nd][b][0] + sLb[l] + sTr[b * 64 + l];
            float v1 = acc[nd][b][1] + sLb[32 + l] + sTr[b * 64 + 32 + l];
            float s = v0 + v1;
            float q = v0 * v0 + v1 * v1;
#pragma unroll
            for (int o = 16; o; o >>= 1) {
                s += __shfl_xor_sync(0xffffffffu, s, o);
                q += __shfl_xor_sync(0xffffffffu, q, o);
            }
            float mu = s * (1.f / 64.f);
            float var = q * (1.f / 64.f) - mu * mu;
            float rs = rsqrtf(var + 1e-5f);
            v0 = (v0 - mu) * rs * sG[l] + sB[l];
            v1 = (v1 - mu) * rs * sG[32 + l] + sB[32 + l];
            v0 = v0 > 0.f ? v0 : expm1f(v0);
            v1 = v1 > 0.f ? v1 : expm1f(v1);
            float xo0 = sXf[row * BFDIM + b * 64 + l];
            float xo1 = sXf[row * BFDIM + b * 64 + 32 + l];
            x[(size_t)n * BFDIM + b * 64 + l] = v0 + xo0;
            x[(size_t)n * BFDIM + b * 64 + 32 + l] = v1 + xo1;
        }
    }
}

// ---------------- launch ----------------
extern "C" void kernel_launch(void* const* d_in, const int* in_sizes, int n_in,
                              void* d_out, int out_size) {
    const int* ei  = (const int*)d_in[0];
    const int* ri  = (const int*)d_in[1];
    const float* bnd = (const float*)d_in[2];
    const float* qi  = (const float*)d_in[3];
    const float* rw  = (const float*)d_in[4];
    const float* rb  = (const float*)d_in[5];
    const float* lw  = (const float*)d_in[6];
    const float* lb  = (const float*)d_in[7];
    const float* trw = (const float*)d_in[8];
    const float* trb = (const float*)d_in[9];
    const float* Wm  = (const float*)d_in[10];
    const float* av  = (const float*)d_in[11];
    const float* lng = (const float*)d_in[12];
    const float* lnb = (const float*)d_in[13];
    float* x = (float*)d_out;

    cudaMemcpyAsync(x, bnd, sizeof(float) * NN * BFDIM, cudaMemcpyDeviceToDevice, 0);
    k_prep_rel<<<16, 256>>>(qi, rw, rb);
    k_prep_wa<<<2, 256>>>(Wm, av);
    k_prep_drel<<<1, 128>>>();
    k_prep_w<<<16, 256>>>(lw);

    for (int it = 0; it < NITER; ++it) {
        k_zero<<<10000, 256>>>();
        k_nx<<<2500, 256>>>(x, it);
        k_tr<<<1, 128>>>(trw, trb);
        k_alpha<<<1250, 256>>>(ei, ri, it);
        k_exp<<<1250, 256>>>(ei);
        k_norm<<<1250, 256>>>(ei);
        for (int lvl = 0; lvl < 4; ++lvl) {
            int shift = 48 - 16 * lvl;
            k_hist<<<1250, 256>>>(shift, lvl == 0 ? 1 : 0);
            k_pick<<<1, 1024>>>(shift, lvl == 0 ? 1 : 0);
        }
        k_scatter<<<40000, 256>>>(x, ei, ri);
        k_epi<<<2500, 128>>>(x, lb, lng, lnb);
    }
}

// round 2
// speedup vs baseline: 1.1605x; 1.1605x over previous
#include <cuda_runtime.h>
#include <cstdint>
#include <math_constants.h>

#define NN 20000
#define NE 320000
#define BFDIM 128
#define FD 64
#define RD 32
#define KSEL 160000
#define NITER 4

typedef unsigned long long ull;

// ---------------- scratch (device globals; no allocation allowed) ----------------
__device__ __align__(16) float g_rel[RD * BFDIM];
__device__ __align__(16) float g_wa[4 * BFDIM];
__device__ float g_drel[4 * RD];
__device__ float g_wsumT[FD * FD];
__device__ float g_w2T[FD * FD];
__device__ float g_tr[BFDIM];
__device__ float g_rsum[BFDIM];
__device__ float g_nx[NN];
__device__ float g_aN[NE];
__device__ __align__(16) float g_scat[NN * BFDIM];
__device__ unsigned g_hist[65536];
__device__ ull g_prefix;
__device__ long long g_remaining;
__device__ ull g_thresh;
// CSR
__device__ int g_srcPtr[NN + 1];
__device__ int g_dstPtr[NN + 1];
__device__ unsigned g_srcCnt[NN];
__device__ unsigned g_dstCnt[NN];
__device__ int g_srcEdges[NE];
__device__ int g_dstEdges[NE];

// ---------------- prep (once per launch) ----------------
__global__ void k_prep_rel(const float* __restrict__ q, const float* __restrict__ rw,
                           const float* __restrict__ rb) {
    int t = blockIdx.x * blockDim.x + threadIdx.x;
    if (t >= 2 * 2048) return;
    int b = t >> 11, j = t & 2047;
    const float* qr = q + b * FD;
    const float* wr = rw + j * FD;
    float s = rb[j];
#pragma unroll 16
    for (int k = 0; k < FD; k++) s += qr[k] * wr[k];
    g_rel[b * (RD * FD) + j] = s;   // flat [B, R*F] == reshape(R,B,F) linear layout
}

__global__ void k_prep_wa(const float* __restrict__ Wm, const float* __restrict__ av) {
    int t = blockIdx.x * blockDim.x + threadIdx.x;
    if (t >= 4 * BFDIM) return;
    int i = t >> 7, j = t & 127;
    float s = 0.f;
#pragma unroll 16
    for (int f = 0; f < FD; f++) s += Wm[j * FD + f] * av[i * FD + f];
    g_wa[t] = s;
}

__global__ void k_prep_drel() {
    int t = blockIdx.x * blockDim.x + threadIdx.x;
    if (t >= 4 * RD) return;
    int i = t >> 5, r = t & 31;
    float s = 0.f;
#pragma unroll 16
    for (int j = 0; j < BFDIM; j++) s += g_rel[r * BFDIM + j] * g_wa[i * BFDIM + j];
    g_drel[t] = s;
}

__global__ void k_prep_w(const float* __restrict__ lw) {
    int t = blockIdx.x * blockDim.x + threadIdx.x;
    if (t >= FD * FD) return;
    int j = t >> 6, f = t & 63;
    float w2 = lw[f * 2 * FD + FD + j];
    g_w2T[j * FD + f] = w2;
    g_wsumT[j * FD + f] = lw[f * 2 * FD + j] + w2;
}

// ---------------- CSR build ----------------
__global__ void k_csr_zero() {
    int i = blockIdx.x * blockDim.x + threadIdx.x;
    if (i < NN) { g_srcCnt[i] = 0u; g_dstCnt[i] = 0u; }
}

__global__ __launch_bounds__(256) void k_csr_count(const int* __restrict__ ei) {
    int e = blockIdx.x * blockDim.x + threadIdx.x;
    if (e >= NE) return;
    atomicAdd(&g_srcCnt[ei[e]], 1u);
    atomicAdd(&g_dstCnt[ei[NE + e]], 1u);
}

__global__ __launch_bounds__(1024) void k_csr_scan() {
    __shared__ unsigned ss[1024];
    int t = threadIdx.x;
    for (int phase = 0; phase < 2; ++phase) {
        unsigned* cnt = phase ? g_dstCnt : g_srcCnt;
        int* ptr = phase ? g_dstPtr : g_srcPtr;
        unsigned loc[20]; unsigned s = 0;
#pragma unroll
        for (int i = 0; i < 20; i++) {
            int idx = t * 20 + i;
            unsigned v = (idx < NN) ? cnt[idx] : 0u;
            loc[i] = s; s += v;
        }
        ss[t] = s;
        __syncthreads();
        for (int off = 1; off < 1024; off <<= 1) {
            unsigned v = (t >= off) ? ss[t - off] : 0u;
            __syncthreads();
            ss[t] += v;
            __syncthreads();
        }
        unsigned base = (t > 0) ? ss[t - 1] : 0u;
#pragma unroll
        for (int i = 0; i < 20; i++) {
            int idx = t * 20 + i;
            if (idx < NN) { ptr[idx] = (int)(base + loc[i]); cnt[idx] = 0u; }
        }
        if (t == 0) ptr[NN] = NE;
        __syncthreads();
    }
}

__global__ __launch_bounds__(256) void k_csr_fill(const int* __restrict__ ei) {
    int e = blockIdx.x * blockDim.x + threadIdx.x;
    if (e >= NE) return;
    int s = ei[e];
    unsigned p = atomicAdd(&g_srcCnt[s], 1u);
    g_srcEdges[g_srcPtr[s] + (int)p] = e;
    int d = ei[NE + e];
    unsigned p2 = atomicAdd(&g_dstCnt[d], 1u);
    g_dstEdges[g_dstPtr[d] + (int)p2] = e;
}

// ---------------- init: x = bnd, nx(it=0), rsum ----------------
__global__ __launch_bounds__(256) void k_init(const float* __restrict__ bnd,
                                              float* __restrict__ x) {
    __shared__ float racc[BFDIM];
    int tid = threadIdx.x;
    if (tid < BFDIM) racc[tid] = 0.f;
    __syncthreads();
    int warp = (blockIdx.x * blockDim.x + tid) >> 5;
    int l = tid & 31;
    if (warp < NN) {
        float4 v = reinterpret_cast<const float4*>(bnd)[(size_t)warp * 32 + l];
        reinterpret_cast<float4*>(x)[(size_t)warp * 32 + l] = v;
        float4 w = reinterpret_cast<const float4*>(g_wa)[l];
        float s = v.x * w.x + v.y * w.y + v.z * w.z + v.w * w.w;
#pragma unroll
        for (int o = 16; o; o >>= 1) s += __shfl_xor_sync(0xffffffffu, s, o);
        if (l == 0) g_nx[warp] = s;
        atomicAdd(&racc[l * 4 + 0], v.x);
        atomicAdd(&racc[l * 4 + 1], v.y);
        atomicAdd(&racc[l * 4 + 2], v.z);
        atomicAdd(&racc[l * 4 + 3], v.w);
    }
    __syncthreads();
    if (tid < BFDIM) atomicAdd(&g_rsum[tid], racc[tid]);
}

// ---------------- trans-readout vector (consumes + zeroes rsum) ----------------
__global__ void k_tr(const float* __restrict__ trw, const float* __restrict__ trb) {
    int t = threadIdx.x;
    if (t >= BFDIM) return;
    int b = t >> 6, f = t & 63;
    const float* r = g_rsum + b * FD;
    float s = trb[f];
    const float inv = 1.f / (float)NN;
#pragma unroll 16
    for (int j = 0; j < FD; j++) s += (r[j] * inv) * trw[f * FD + j];
    __syncthreads();
    g_tr[t] = s;
    g_rsum[t] = 0.f;
}

// ---------------- fused per-node softmax + level-0 histogram ----------------
// warp per node (grid-stride). Privatized u16-packed shared histogram (128KB dyn).
__global__ __launch_bounds__(512) void k_soft(const int* __restrict__ ri, int it) {
    extern __shared__ unsigned sh[];   // 32768 words = 65536 u16 bins
    int tid = threadIdx.x;
    for (int i = tid; i < 32768; i += 512) sh[i] = 0u;
    __syncthreads();
    int l = tid & 31;
    int warp = (blockIdx.x * 512 + tid) >> 5;
    int totalWarps = gridDim.x * 16;
    const float* drel = g_drel + it * RD;
    for (int n = warp; n < NN; n += totalWarps) {
        int beg = g_srcPtr[n], end = g_srcPtr[n + 1];
        if (beg == end) continue;
        float nx = g_nx[n];
        float m = -CUDART_INF_F;
        for (int k = beg + l; k < end; k += 32) {
            int e = g_srcEdges[k];
            float t = nx + drel[ri[e]];
            t = t > 0.f ? t : 0.2f * t;
            m = fmaxf(m, t);
        }
#pragma unroll
        for (int o = 16; o; o >>= 1) m = fmaxf(m, __shfl_xor_sync(0xffffffffu, m, o));
        float sum = 0.f;
        for (int k = beg + l; k < end; k += 32) {
            int e = g_srcEdges[k];
            float t = nx + drel[ri[e]];
            t = t > 0.f ? t : 0.2f * t;
            sum += expf(t - m);
        }
#pragma unroll
        for (int o = 16; o; o >>= 1) sum += __shfl_xor_sync(0xffffffffu, sum, o);
        float invd = 1.f / (sum + 1e-16f);
        for (int k = beg + l; k < end; k += 32) {
            int e = g_srcEdges[k];
            float t = nx + drel[ri[e]];
            t = t > 0.f ? t : 0.2f * t;
            float a = expf(t - m) * invd;
            g_aN[e] = a;
            unsigned d = __float_as_uint(a) >> 16;   // level-0 digit (alpha >= 0)
            atomicAdd(&sh[d >> 1], (d & 1) ? 65536u : 1u);
        }
    }
    __syncthreads();
    for (int i = tid; i < 32768; i += 512) {
        unsigned w = sh[i];
        if (w) {
            unsigned lo = w & 0xFFFFu, hi = w >> 16;
            if (lo) atomicAdd(&g_hist[2 * i], lo);
            if (hi) atomicAdd(&g_hist[2 * i + 1], hi);
        }
    }
}

// ---------------- radix levels 1..3 histogram (privatized) ----------------
__device__ __forceinline__ ull edge_key(int e) {
    return ((ull)__float_as_uint(g_aN[e]) << 32) | (unsigned)(0xFFFFFFFFu - (unsigned)e);
}

__global__ __launch_bounds__(512) void k_hist(int shift) {
    extern __shared__ unsigned sh[];
    int tid = threadIdx.x;
    for (int i = tid; i < 32768; i += 512) sh[i] = 0u;
    __syncthreads();
    ull pref = g_prefix >> (shift + 16);
    int stride = gridDim.x * 512;
    for (int e = blockIdx.x * 512 + tid; e < NE; e += stride) {
        ull key = edge_key(e);
        if ((key >> (shift + 16)) == pref) {
            unsigned d = (unsigned)(key >> shift) & 0xFFFFu;
            atomicAdd(&sh[d >> 1], (d & 1) ? 65536u : 1u);
        }
    }
    __syncthreads();
    for (int i = tid; i < 32768; i += 512) {
        unsigned w = sh[i];
        if (w) {
            unsigned lo = w & 0xFFFFu, hi = w >> 16;
            if (lo) atomicAdd(&g_hist[2 * i], lo);
            if (hi) atomicAdd(&g_hist[2 * i + 1], hi);
        }
    }
}

__global__ __launch_bounds__(1024) void k_pick(int shift, int first) {
    __shared__ unsigned ssum[1024];
    int t = threadIdx.x;
    int base = 65535 - t * 64;
    unsigned cs = 0;
#pragma unroll 8
    for (int u = 0; u < 64; ++u) cs += g_hist[base - u];
    ssum[t] = cs;
    __syncthreads();
    for (int off = 1; off < 1024; off <<= 1) {
        unsigned v = (t >= off) ? ssum[t - off] : 0u;
        __syncthreads();
        ssum[t] += v;
        __syncthreads();
    }
    long long R = first ? (long long)KSEL : g_remaining;
    ull pre = first ? 0ull : g_prefix;
    long long incl = (long long)ssum[t];
    long long cumBefore = incl - (long long)cs;
    if (cumBefore < R && R <= incl) {
        long long cum = cumBefore;
        for (int u = 0; u < 64; ++u) {
            int d = base - u;
            unsigned h = g_hist[d];
            cum += h;
            if (cum >= R) {
                ull np = pre | ((ull)d << shift);
                g_prefix = np;
                g_remaining = R - (cum - h);
                if (shift == 0) g_thresh = np;
                break;
            }
        }
    }
    for (int u = 0; u < 64; ++u) g_hist[base - u] = 0u;
}

// ---------------- scatter by dst (warp per node, no atomics, no zeroing) -------
__global__ __launch_bounds__(256) void k_scatter(const float* __restrict__ x,
                                                 const int* __restrict__ ei,
                                                 const int* __restrict__ ri) {
    int warp = (blockIdx.x * blockDim.x + threadIdx.x) >> 5;
    int l = threadIdx.x & 31;
    if (warp >= NN) return;
    int beg = g_dstPtr[warp], end = g_dstPtr[warp + 1];
    ull th = g_thresh;
    float4 acc = make_float4(0.f, 0.f, 0.f, 0.f);
    for (int k = beg; k < end; ++k) {
        int e = g_dstEdges[k];
        float a = g_aN[e];
        ull key = ((ull)__float_as_uint(a) << 32) | (unsigned)(0xFFFFFFFFu - (unsigned)e);
        if (key < th) continue;
        int s = ei[e], r = ri[e];
        float4 xv = reinterpret_cast<const float4*>(x)[(size_t)s * 32 + l];
        float4 rv = reinterpret_cast<const float4*>(g_rel)[r * 32 + l];
        acc.x += a * (xv.x + rv.x);
        acc.y += a * (xv.y + rv.y);
        acc.z += a * (xv.z + rv.z);
        acc.w += a * (xv.w + rv.w);
    }
    reinterpret_cast<float4*>(g_scat)[(size_t)warp * 32 + l] = acc;
}

// ------ fused layer linear + broadcast + LN + ELU + residual + next nx/rsum ----
__global__ __launch_bounds__(128) void k_epi(float* __restrict__ x,
                                             const float* __restrict__ lb,
                                             const float* __restrict__ lng,
                                             const float* __restrict__ lnb,
                                             int it) {
    __shared__ float sWs[FD * FD];
    __shared__ float sW2[FD * FD];
    __shared__ float sTr[BFDIM];
    __shared__ float sWa[BFDIM];
    __shared__ float racc[BFDIM];
    __shared__ float sLb[FD], sG[FD], sB[FD];
    __shared__ float4 sX[8][32];
    __shared__ float4 sS[8][32];
    int tid = threadIdx.x;
    for (int i = tid; i < FD * FD; i += 128) { sWs[i] = g_wsumT[i]; sW2[i] = g_w2T[i]; }
    if (tid < BFDIM) {
        sTr[tid] = g_tr[tid];
        sWa[tid] = (it < 3) ? g_wa[(it + 1) * BFDIM + tid] : 0.f;
        racc[tid] = 0.f;
    }
    if (tid < FD) { sLb[tid] = lb[tid]; sG[tid] = lng[tid]; sB[tid] = lnb[tid]; }
    __syncthreads();
    int w = tid >> 5, l = tid & 31;
    int nbase = blockIdx.x * 8 + w * 2;
    int row0 = w * 2, row1 = w * 2 + 1;
#pragma unroll
    for (int nd = 0; nd < 2; ++nd) {
        int n = nbase + nd;
        sX[row0 + nd][l] = reinterpret_cast<const float4*>(x)[(size_t)n * 32 + l];
        sS[row0 + nd][l] = reinterpret_cast<const float4*>(g_scat)[(size_t)n * 32 + l];
    }
    __syncwarp();

    float acc[2][2][2] = {};
    for (int jv = 0; jv < 16; ++jv) {
        float4 X0a = sX[row0][jv], X1a = sX[row0][16 + jv];
        float4 S0a = sS[row0][jv], S1a = sS[row0][16 + jv];
        float4 X0b = sX[row1][jv], X1b = sX[row1][16 + jv];
        float4 S0b = sS[row1][jv], S1b = sS[row1][16 + jv];
        const float* x0a = (const float*)&X0a; const float* x1a = (const float*)&X1a;
        const float* s0a = (const float*)&S0a; const float* s1a = (const float*)&S1a;
        const float* x0b = (const float*)&X0b; const float* x1b = (const float*)&X1b;
        const float* s0b = (const float*)&S0b; const float* s1b = (const float*)&S1b;
#pragma unroll
        for (int u = 0; u < 4; ++u) {
            int j = jv * 4 + u;
            float wA0 = sWs[j * FD + l], wA1 = sWs[j * FD + 32 + l];
            float wB0 = sW2[j * FD + l], wB1 = sW2[j * FD + 32 + l];
            acc[0][0][0] += x0a[u] * wA0 + s0a[u] * wB0;
            acc[0][0][1] += x0a[u] * wA1 + s0a[u] * wB1;
            acc[0][1][0] += x1a[u] * wA0 + s1a[u] * wB0;
            acc[0][1][1] += x1a[u] * wA1 + s1a[u] * wB1;
            acc[1][0][0] += x0b[u] * wA0 + s0b[u] * wB0;
            acc[1][0][1] += x0b[u] * wA1 + s0b[u] * wB1;
            acc[1][1][0] += x1b[u] * wA0 + s1b[u] * wB0;
            acc[1][1][1] += x1b[u] * wA1 + s1b[u] * wB1;
        }
    }

    const float* sXf = (const float*)sX;
#pragma unroll
    for (int nd = 0; nd < 2; ++nd) {
        int n = nbase + nd;
        int row = row0 + nd;
        float nxacc = 0.f;
#pragma unroll
        for (int b = 0; b < 2; ++b) {
            float v0 = acc[nd][b][0] + sLb[l] + sTr[b * 64 + l];
            float v1 = acc[nd][b][1] + sLb[32 + l] + sTr[b * 64 + 32 + l];
            float s = v0 + v1;
            float q = v0 * v0 + v1 * v1;
#pragma unroll
            for (int o = 16; o; o >>= 1) {
                s += __shfl_xor_sync(0xffffffffu, s, o);
                q += __shfl_xor_sync(0xffffffffu, q, o);
            }
            float mu = s * (1.f / 64.f);
            float var = q * (1.f / 64.f) - mu * mu;
            float rs = rsqrtf(var + 1e-5f);
            v0 = (v0 - mu) * rs * sG[l] + sB[l];
            v1 = (v1 - mu) * rs * sG[32 + l] + sB[32 + l];
            v0 = v0 > 0.f ? v0 : expm1f(v0);
            v1 = v1 > 0.f ? v1 : expm1f(v1);
            float xn0 = v0 + sXf[row * BFDIM + b * 64 + l];
            float xn1 = v1 + sXf[row * BFDIM + b * 64 + 32 + l];
            x[(size_t)n * BFDIM + b * 64 + l] = xn0;
            x[(size_t)n * BFDIM + b * 64 + 32 + l] = xn1;
            if (it < 3) {
                nxacc += xn0 * sWa[b * 64 + l] + xn1 * sWa[b * 64 + 32 + l];
                atomicAdd(&racc[b * 64 + l], xn0);
                atomicAdd(&racc[b * 64 + 32 + l], xn1);
            }
        }
        if (it < 3) {
#pragma unroll
            for (int o = 16; o; o >>= 1) nxacc += __shfl_xor_sync(0xffffffffu, nxacc, o);
            if (l == 0) g_nx[n] = nxacc;
        }
    }
    __syncthreads();
    if (it < 3 && tid < BFDIM) atomicAdd(&g_rsum[tid], racc[tid]);
}

// ---------------- launch ----------------
extern "C" void kernel_launch(void* const* d_in, const int* in_sizes, int n_in,
                              void* d_out, int out_size) {
    const int* ei  = (const int*)d_in[0];
    const int* ri  = (const int*)d_in[1];
    const float* bnd = (const float*)d_in[2];
    const float* qi  = (const float*)d_in[3];
    const float* rw  = (const float*)d_in[4];
    const float* rb  = (const float*)d_in[5];
    const float* lw  = (const float*)d_in[6];
    const float* lb  = (const float*)d_in[7];
    const float* trw = (const float*)d_in[8];
    const float* trb = (const float*)d_in[9];
    const float* Wm  = (const float*)d_in[10];
    const float* av  = (const float*)d_in[11];
    const float* lng = (const float*)d_in[12];
    const float* lnb = (const float*)d_in[13];
    float* x = (float*)d_out;

    static int attr_done = 0;
    if (!attr_done) {
        cudaFuncSetAttribute(k_soft, cudaFuncAttributeMaxDynamicSharedMemorySize, 131072);
        cudaFuncSetAttribute(k_hist, cudaFuncAttributeMaxDynamicSharedMemorySize, 131072);
        attr_done = 1;
    }

    k_prep_rel<<<16, 256>>>(qi, rw, rb);
    k_prep_wa<<<2, 256>>>(Wm, av);
    k_prep_drel<<<1, 128>>>();
    k_prep_w<<<16, 256>>>(lw);
    k_csr_zero<<<79, 256>>>();
    k_csr_count<<<1250, 256>>>(ei);
    k_csr_scan<<<1, 1024>>>();
    k_csr_fill<<<1250, 256>>>(ei);
    k_init<<<2500, 256>>>(bnd, x);

    for (int it = 0; it < NITER; ++it) {
        k_tr<<<1, 128>>>(trw, trb);
        k_soft<<<148, 512, 131072>>>(ri, it);
        k_pick<<<1, 1024>>>(48, 1);
        k_hist<<<148, 512, 131072>>>(32);
        k_pick<<<1, 1024>>>(32, 0);
        k_hist<<<148, 512, 131072>>>(16);
        k_pick<<<1, 1024>>>(16, 0);
        k_hist<<<148, 512, 131072>>>(0);
        k_pick<<<1, 1024>>>(0, 0);
        k_scatter<<<2500, 256>>>(x, ei, ri);
        k_epi<<<2500, 128>>>(x, lb, lng, lnb, it);
    }
}

// round 3
// speedup vs baseline: 3.3101x; 2.8524x over previous
#include <cuda_runtime.h>
#include <cstdint>
#include <math_constants.h>

#define NN 20000
#define NE 320000
#define BFDIM 128
#define FD 64
#define RD 32
#define KSEL 160000
#define NITER 4

typedef unsigned long long ull;

// ---------------- scratch ----------------
__device__ __align__(16) float g_rel[RD * BFDIM];
__device__ __align__(16) float g_wa[4 * BFDIM];
__device__ float g_drel[4 * RD];
__device__ float g_wsumT[FD * FD];
__device__ float g_w2T[FD * FD];
__device__ float g_tr[BFDIM];
__device__ float g_rsum[BFDIM];
__device__ float g_nx[NN];
__device__ float g_aN[NE];
__device__ __align__(16) float g_scat[NN * BFDIM];
__device__ __align__(16) unsigned g_hist[65536];
__device__ __align__(16) unsigned g_coarse[256];
__device__ unsigned g_d0;
__device__ unsigned g_Talpha;
__device__ unsigned g_eqCount;
__device__ int g_eq[8192];
__device__ long long g_remaining;
__device__ ull g_thresh;
// CSR
__device__ int g_srcPtr[NN + 1];
__device__ int g_dstPtr[NN + 1];
__device__ unsigned g_srcCnt[NN];
__device__ unsigned g_dstCnt[NN];
__device__ int g_srcEdges[NE];
__device__ int g_dstEdges[NE];

// ---------------- prep (once per launch) ----------------
__global__ void k_prep_rel(const float* __restrict__ q, const float* __restrict__ rw,
                           const float* __restrict__ rb) {
    int t = blockIdx.x * blockDim.x + threadIdx.x;
    if (t >= 2 * 2048) return;
    int b = t >> 11, j = t & 2047;
    const float* qr = q + b * FD;
    const float* wr = rw + j * FD;
    float s = rb[j];
#pragma unroll 16
    for (int k = 0; k < FD; k++) s += qr[k] * wr[k];
    g_rel[b * (RD * FD) + j] = s;
}

__global__ void k_prep_wa(const float* __restrict__ Wm, const float* __restrict__ av) {
    int t = blockIdx.x * blockDim.x + threadIdx.x;
    if (t >= 4 * BFDIM) return;
    int i = t >> 7, j = t & 127;
    float s = 0.f;
#pragma unroll 16
    for (int f = 0; f < FD; f++) s += Wm[j * FD + f] * av[i * FD + f];
    g_wa[t] = s;
}

__global__ void k_prep_drel() {
    int t = blockIdx.x * blockDim.x + threadIdx.x;
    if (t >= 4 * RD) return;
    int i = t >> 5, r = t & 31;
    float s = 0.f;
#pragma unroll 16
    for (int j = 0; j < BFDIM; j++) s += g_rel[r * BFDIM + j] * g_wa[i * BFDIM + j];
    g_drel[t] = s;
}

__global__ void k_prep_w(const float* __restrict__ lw) {
    int t = blockIdx.x * blockDim.x + threadIdx.x;
    if (t >= FD * FD) return;
    int j = t >> 6, f = t & 63;
    float w2 = lw[f * 2 * FD + FD + j];
    g_w2T[j * FD + f] = w2;
    g_wsumT[j * FD + f] = lw[f * 2 * FD + j] + w2;
}

// ---------------- CSR build ----------------
__global__ void k_csr_zero() {
    int i = blockIdx.x * blockDim.x + threadIdx.x;
    if (i < NN) { g_srcCnt[i] = 0u; g_dstCnt[i] = 0u; }
}

__global__ __launch_bounds__(256) void k_csr_count(const int* __restrict__ ei) {
    int e = blockIdx.x * blockDim.x + threadIdx.x;
    if (e >= NE) return;
    atomicAdd(&g_srcCnt[ei[e]], 1u);
    atomicAdd(&g_dstCnt[ei[NE + e]], 1u);
}

__global__ __launch_bounds__(1024) void k_csr_scan() {
    __shared__ unsigned ss[1024];
    int t = threadIdx.x;
    for (int phase = 0; phase < 2; ++phase) {
        unsigned* cnt = phase ? g_dstCnt : g_srcCnt;
        int* ptr = phase ? g_dstPtr : g_srcPtr;
        unsigned loc[20]; unsigned s = 0;
#pragma unroll
        for (int i = 0; i < 20; i++) {
            int idx = t * 20 + i;
            unsigned v = (idx < NN) ? cnt[idx] : 0u;
            loc[i] = s; s += v;
        }
        ss[t] = s;
        __syncthreads();
        for (int off = 1; off < 1024; off <<= 1) {
            unsigned v = (t >= off) ? ss[t - off] : 0u;
            __syncthreads();
            ss[t] += v;
            __syncthreads();
        }
        unsigned base = (t > 0) ? ss[t - 1] : 0u;
#pragma unroll
        for (int i = 0; i < 20; i++) {
            int idx = t * 20 + i;
            if (idx < NN) { ptr[idx] = (int)(base + loc[i]); cnt[idx] = 0u; }
        }
        if (t == 0) ptr[NN] = NE;
        __syncthreads();
    }
}

__global__ __launch_bounds__(256) void k_csr_fill(const int* __restrict__ ei) {
    int e = blockIdx.x * blockDim.x + threadIdx.x;
    if (e >= NE) return;
    int s = ei[e];
    unsigned p = atomicAdd(&g_srcCnt[s], 1u);
    g_srcEdges[g_srcPtr[s] + (int)p] = e;
    int d = ei[NE + e];
    unsigned p2 = atomicAdd(&g_dstCnt[d], 1u);
    g_dstEdges[g_dstPtr[d] + (int)p2] = e;
}

// ---------------- init: x = bnd, nx(it=0), rsum ----------------
__global__ __launch_bounds__(256) void k_init(const float* __restrict__ bnd,
                                              float* __restrict__ x) {
    __shared__ float racc[BFDIM];
    int tid = threadIdx.x;
    if (tid < BFDIM) racc[tid] = 0.f;
    __syncthreads();
    int warp = (blockIdx.x * blockDim.x + tid) >> 5;
    int l = tid & 31;
    if (warp < NN) {
        float4 v = reinterpret_cast<const float4*>(bnd)[(size_t)warp * 32 + l];
        reinterpret_cast<float4*>(x)[(size_t)warp * 32 + l] = v;
        float4 w = reinterpret_cast<const float4*>(g_wa)[l];
        float s = v.x * w.x + v.y * w.y + v.z * w.z + v.w * w.w;
#pragma unroll
        for (int o = 16; o; o >>= 1) s += __shfl_xor_sync(0xffffffffu, s, o);
        if (l == 0) g_nx[warp] = s;
        atomicAdd(&racc[l * 4 + 0], v.x);
        atomicAdd(&racc[l * 4 + 1], v.y);
        atomicAdd(&racc[l * 4 + 2], v.z);
        atomicAdd(&racc[l * 4 + 3], v.w);
    }
    __syncthreads();
    if (tid < BFDIM) atomicAdd(&g_rsum[tid], racc[tid]);
}

// ---------------- trans-readout vector (consumes + zeroes rsum) ----------------
__global__ void k_tr(const float* __restrict__ trw, const float* __restrict__ trb) {
    int t = threadIdx.x;
    if (t >= BFDIM) return;
    int b = t >> 6, f = t & 63;
    const float* r = g_rsum + b * FD;
    float s = trb[f];
    const float inv = 1.f / (float)NN;
#pragma unroll 16
    for (int j = 0; j < FD; j++) s += (r[j] * inv) * trw[f * FD + j];
    __syncthreads();
    g_tr[t] = s;
    g_rsum[t] = 0.f;
}

// ---------------- merge helper: smem packed-u16 hist -> global fine + coarse ----
__device__ __forceinline__ void merge_hist(unsigned* sh, int tid) {
    int w = tid >> 5, l = tid & 31;
    for (int g = w; g < 256; g += 16) {
        unsigned gsum = 0;
        int base = g * 128;          // words of this group
#pragma unroll
        for (int j = 0; j < 4; ++j) {
            int wi = base + j * 32 + l;
            unsigned word = sh[wi];
            if (word) {
                unsigned lo = word & 0xFFFFu, hi = word >> 16;
                if (lo) atomicAdd(&g_hist[2 * wi], lo);
                if (hi) atomicAdd(&g_hist[2 * wi + 1], hi);
                gsum += lo + hi;
            }
        }
#pragma unroll
        for (int o = 16; o; o >>= 1) gsum += __shfl_xor_sync(0xffffffffu, gsum, o);
        if (l == 0 && gsum) atomicAdd(&g_coarse[g], gsum);
    }
}

// ---------------- fused per-node softmax + level-0 histogram ----------------
__global__ __launch_bounds__(512) void k_soft(const int* __restrict__ ri, int it) {
    extern __shared__ unsigned sh[];   // 32768 words = 65536 u16 bins
    int tid = threadIdx.x;
    for (int i = tid; i < 32768; i += 512) sh[i] = 0u;
    __syncthreads();
    int l = tid & 31;
    int warp = (blockIdx.x * 512 + tid) >> 5;
    int totalWarps = gridDim.x * 16;
    const float* drel = g_drel + it * RD;
    for (int n = warp; n < NN; n += totalWarps) {
        int beg = g_srcPtr[n], end = g_srcPtr[n + 1];
        if (beg == end) continue;
        float nx = g_nx[n];
        float m = -CUDART_INF_F;
        for (int k = beg + l; k < end; k += 32) {
            int e = g_srcEdges[k];
            float t = nx + drel[ri[e]];
            t = t > 0.f ? t : 0.2f * t;
            m = fmaxf(m, t);
        }
#pragma unroll
        for (int o = 16; o; o >>= 1) m = fmaxf(m, __shfl_xor_sync(0xffffffffu, m, o));
        float sum = 0.f;
        for (int k = beg + l; k < end; k += 32) {
            int e = g_srcEdges[k];
            float t = nx + drel[ri[e]];
            t = t > 0.f ? t : 0.2f * t;
            sum += expf(t - m);
        }
#pragma unroll
        for (int o = 16; o; o >>= 1) sum += __shfl_xor_sync(0xffffffffu, sum, o);
        float invd = 1.f / (sum + 1e-16f);
        for (int k = beg + l; k < end; k += 32) {
            int e = g_srcEdges[k];
            float t = nx + drel[ri[e]];
            t = t > 0.f ? t : 0.2f * t;
            float a = expf(t - m) * invd;
            g_aN[e] = a;
            unsigned d = __float_as_uint(a) >> 16;
            atomicAdd(&sh[d >> 1], (d & 1) ? 65536u : 1u);
        }
    }
    __syncthreads();
    merge_hist(sh, tid);
}

// ---------------- level-1 histogram (low 16 alpha bits, filtered) ----------------
__global__ __launch_bounds__(512) void k_hist1(int dummy) {
    extern __shared__ unsigned sh[];
    int tid = threadIdx.x;
    for (int i = tid; i < 32768; i += 512) sh[i] = 0u;
    __syncthreads();
    unsigned d0 = g_d0;
    int stride = gridDim.x * 512;
    for (int e = blockIdx.x * 512 + tid; e < NE; e += stride) {
        unsigned bits = __float_as_uint(g_aN[e]);
        if ((bits >> 16) == d0) {
            unsigned d = bits & 0xFFFFu;
            atomicAdd(&sh[d >> 1], (d & 1) ? 65536u : 1u);
        }
    }
    __syncthreads();
    merge_hist(sh, tid);
}

// ---------------- hierarchical pick: coarse group then fine digit ----------------
__global__ __launch_bounds__(1024) void k_pick(int level) {
    __shared__ unsigned s[256];
    __shared__ unsigned sc[256];
    __shared__ unsigned sGrp, sR2;
    int t = threadIdx.x;
    long long R = (level == 0) ? (long long)KSEL : g_remaining;
    // ---- coarse ----
    if (t < 256) s[t] = g_coarse[t];
    __syncthreads();
    if (t < 256) sc[t] = s[255 - t];
    __syncthreads();
    for (int off = 1; off < 256; off <<= 1) {
        unsigned v = (t < 256 && t >= off) ? sc[t - off] : 0u;
        __syncthreads();
        if (t < 256) sc[t] += v;
        __syncthreads();
    }
    if (t < 256) {
        long long incl = (long long)sc[t];
        long long before = incl - (long long)s[255 - t];
        if (before < R && R <= incl) { sGrp = 255 - t; sR2 = (unsigned)(R - before); }
    }
    __syncthreads();
    unsigned grp = sGrp;
    long long R2 = (long long)sR2;
    // ---- fine ----
    if (t < 256) s[t] = g_hist[grp * 256 + t];
    __syncthreads();
    if (t < 256) sc[t] = s[255 - t];
    __syncthreads();
    for (int off = 1; off < 256; off <<= 1) {
        unsigned v = (t < 256 && t >= off) ? sc[t - off] : 0u;
        __syncthreads();
        if (t < 256) sc[t] += v;
        __syncthreads();
    }
    if (t < 256) {
        long long incl = (long long)sc[t];
        long long before = incl - (long long)s[255 - t];
        if (before < R2 && R2 <= incl) {
            unsigned digit = grp * 256 + (255 - t);
            long long rem = R2 - before;
            if (level == 0) {
                g_d0 = digit;
                g_remaining = rem;
            } else {
                g_Talpha = (g_d0 << 16) | digit;
                g_remaining = rem;
                g_eqCount = 0u;
            }
        }
    }
    // ---- clear for next level / iteration ----
    __syncthreads();
    uint4 z = make_uint4(0u, 0u, 0u, 0u);
    uint4* H = reinterpret_cast<uint4*>(g_hist);
    for (int i = t; i < 16384; i += 1024) H[i] = z;
    if (t < 64) reinterpret_cast<uint4*>(g_coarse)[t] = z;
}

// ---------------- collect edges equal to threshold alpha ----------------
__global__ __launch_bounds__(256) void k_collect() {
    unsigned T = g_Talpha;
    int e = blockIdx.x * blockDim.x + threadIdx.x;
    if (e >= NE) return;
    if (__float_as_uint(g_aN[e]) == T) {
        unsigned p = atomicAdd(&g_eqCount, 1u);
        if (p < 8192u) g_eq[p] = e;
    }
}

// ---------------- resolve r-th smallest equal index -> 64-bit threshold --------
__global__ __launch_bounds__(1024) void k_resolve() {
    __shared__ int se[8192];
    int c = (int)min(g_eqCount, 8192u);
    int r = (int)g_remaining;
    unsigned T = g_Talpha;
    int t = threadIdx.x;
    for (int i = t; i < c; i += 1024) se[i] = g_eq[i];
    __syncthreads();
    for (int i = t; i < c; i += 1024) {
        int e = se[i];
        int cnt = 0;
        for (int j = 0; j < c; ++j) cnt += (se[j] < e) ? 1 : 0;
        if (cnt == r - 1)
            g_thresh = ((ull)T << 32) | (unsigned)(0xFFFFFFFFu - (unsigned)e);
    }
}

// ---------------- scatter by dst (warp per node, no atomics) ----------------
__global__ __launch_bounds__(256) void k_scatter(const float* __restrict__ x,
                                                 const int* __restrict__ ei,
                                                 const int* __restrict__ ri) {
    int warp = (blockIdx.x * blockDim.x + threadIdx.x) >> 5;
    int l = threadIdx.x & 31;
    if (warp >= NN) return;
    int beg = g_dstPtr[warp], end = g_dstPtr[warp + 1];
    ull th = g_thresh;
    float4 acc = make_float4(0.f, 0.f, 0.f, 0.f);
    for (int k = beg; k < end; ++k) {
        int e = g_dstEdges[k];
        float a = g_aN[e];
        ull key = ((ull)__float_as_uint(a) << 32) | (unsigned)(0xFFFFFFFFu - (unsigned)e);
        if (key < th) continue;
        int s = ei[e], r = ri[e];
        float4 xv = reinterpret_cast<const float4*>(x)[(size_t)s * 32 + l];
        float4 rv = reinterpret_cast<const float4*>(g_rel)[r * 32 + l];
        acc.x += a * (xv.x + rv.x);
        acc.y += a * (xv.y + rv.y);
        acc.z += a * (xv.z + rv.z);
        acc.w += a * (xv.w + rv.w);
    }
    reinterpret_cast<float4*>(g_scat)[(size_t)warp * 32 + l] = acc;
}

// ------ fused layer linear + broadcast + LN + ELU + residual + next nx/rsum ----
__global__ __launch_bounds__(128) void k_epi(float* __restrict__ x,
                                             const float* __restrict__ lb,
                                             const float* __restrict__ lng,
                                             const float* __restrict__ lnb,
                                             int it) {
    __shared__ float sWs[FD * FD];
    __shared__ float sW2[FD * FD];
    __shared__ float sTr[BFDIM];
    __shared__ float sWa[BFDIM];
    __shared__ float racc[BFDIM];
    __shared__ float sLb[FD], sG[FD], sB[FD];
    __shared__ float4 sX[8][32];
    __shared__ float4 sS[8][32];
    int tid = threadIdx.x;
    for (int i = tid; i < FD * FD; i += 128) { sWs[i] = g_wsumT[i]; sW2[i] = g_w2T[i]; }
    if (tid < BFDIM) {
        sTr[tid] = g_tr[tid];
        sWa[tid] = (it < 3) ? g_wa[(it + 1) * BFDIM + tid] : 0.f;
        racc[tid] = 0.f;
    }
    if (tid < FD) { sLb[tid] = lb[tid]; sG[tid] = lng[tid]; sB[tid] = lnb[tid]; }
    __syncthreads();
    int w = tid >> 5, l = tid & 31;
    int nbase = blockIdx.x * 8 + w * 2;
    int row0 = w * 2, row1 = w * 2 + 1;
#pragma unroll
    for (int nd = 0; nd < 2; ++nd) {
        int n = nbase + nd;
        sX[row0 + nd][l] = reinterpret_cast<const float4*>(x)[(size_t)n * 32 + l];
        sS[row0 + nd][l] = reinterpret_cast<const float4*>(g_scat)[(size_t)n * 32 + l];
    }
    __syncwarp();

    float acc[2][2][2] = {};
    for (int jv = 0; jv < 16; ++jv) {
        float4 X0a = sX[row0][jv], X1a = sX[row0][16 + jv];
        float4 S0a = sS[row0][jv], S1a = sS[row0][16 + jv];
        float4 X0b = sX[row1][jv], X1b = sX[row1][16 + jv];
        float4 S0b = sS[row1][jv], S1b = sS[row1][16 + jv];
        const float* x0a = (const float*)&X0a; const float* x1a = (const float*)&X1a;
        const float* s0a = (const float*)&S0a; const float* s1a = (const float*)&S1a;
        const float* x0b = (const float*)&X0b; const float* x1b = (const float*)&X1b;
        const float* s0b = (const float*)&S0b; const float* s1b = (const float*)&S1b;
#pragma unroll
        for (int u = 0; u < 4; ++u) {
            int j = jv * 4 + u;
            float wA0 = sWs[j * FD + l], wA1 = sWs[j * FD + 32 + l];
            float wB0 = sW2[j * FD + l], wB1 = sW2[j * FD + 32 + l];
            acc[0][0][0] += x0a[u] * wA0 + s0a[u] * wB0;
            acc[0][0][1] += x0a[u] * wA1 + s0a[u] * wB1;
            acc[0][1][0] += x1a[u] * wA0 + s1a[u] * wB0;
            acc[0][1][1] += x1a[u] * wA1 + s1a[u] * wB1;
            acc[1][0][0] += x0b[u] * wA0 + s0b[u] * wB0;
            acc[1][0][1] += x0b[u] * wA1 + s0b[u] * wB1;
            acc[1][1][0] += x1b[u] * wA0 + s1b[u] * wB0;
            acc[1][1][1] += x1b[u] * wA1 + s1b[u] * wB1;
        }
    }

    const float* sXf = (const float*)sX;
#pragma unroll
    for (int nd = 0; nd < 2; ++nd) {
        int n = nbase + nd;
        int row = row0 + nd;
        float nxacc = 0.f;
#pragma unroll
        for (int b = 0; b < 2; ++b) {
            float v0 = acc[nd][b][0] + sLb[l] + sTr[b * 64 + l];
            float v1 = acc[nd][b][1] + sLb[32 + l] + sTr[b * 64 + 32 + l];
            float s = v0 + v1;
            float q = v0 * v0 + v1 * v1;
#pragma unroll
            for (int o = 16; o; o >>= 1) {
                s += __shfl_xor_sync(0xffffffffu, s, o);
                q += __shfl_xor_sync(0xffffffffu, q, o);
            }
            float mu = s * (1.f / 64.f);
            float var = q * (1.f / 64.f) - mu * mu;
            float rs = rsqrtf(var + 1e-5f);
            v0 = (v0 - mu) * rs * sG[l] + sB[l];
            v1 = (v1 - mu) * rs * sG[32 + l] + sB[32 + l];
            v0 = v0 > 0.f ? v0 : expm1f(v0);
            v1 = v1 > 0.f ? v1 : expm1f(v1);
            float xn0 = v0 + sXf[row * BFDIM + b * 64 + l];
            float xn1 = v1 + sXf[row * BFDIM + b * 64 + 32 + l];
            x[(size_t)n * BFDIM + b * 64 + l] = xn0;
            x[(size_t)n * BFDIM + b * 64 + 32 + l] = xn1;
            if (it < 3) {
                nxacc += xn0 * sWa[b * 64 + l] + xn1 * sWa[b * 64 + 32 + l];
                atomicAdd(&racc[b * 64 + l], xn0);
                atomicAdd(&racc[b * 64 + 32 + l], xn1);
            }
        }
        if (it < 3) {
#pragma unroll
            for (int o = 16; o; o >>= 1) nxacc += __shfl_xor_sync(0xffffffffu, nxacc, o);
            if (l == 0) g_nx[n] = nxacc;
        }
    }
    __syncthreads();
    if (it < 3 && tid < BFDIM) atomicAdd(&g_rsum[tid], racc[tid]);
}

// ---------------- launch ----------------
extern "C" void kernel_launch(void* const* d_in, const int* in_sizes, int n_in,
                              void* d_out, int out_size) {
    const int* ei  = (const int*)d_in[0];
    const int* ri  = (const int*)d_in[1];
    const float* bnd = (const float*)d_in[2];
    const float* qi  = (const float*)d_in[3];
    const float* rw  = (const float*)d_in[4];
    const float* rb  = (const float*)d_in[5];
    const float* lw  = (const float*)d_in[6];
    const float* lb  = (const float*)d_in[7];
    const float* trw = (const float*)d_in[8];
    const float* trb = (const float*)d_in[9];
    const float* Wm  = (const float*)d_in[10];
    const float* av  = (const float*)d_in[11];
    const float* lng = (const float*)d_in[12];
    const float* lnb = (const float*)d_in[13];
    float* x = (float*)d_out;

    static int attr_done = 0;
    if (!attr_done) {
        cudaFuncSetAttribute(k_soft, cudaFuncAttributeMaxDynamicSharedMemorySize, 131072);
        cudaFuncSetAttribute(k_hist1, cudaFuncAttributeMaxDynamicSharedMemorySize, 131072);
        attr_done = 1;
    }

    k_prep_rel<<<16, 256>>>(qi, rw, rb);
    k_prep_wa<<<2, 256>>>(Wm, av);
    k_prep_drel<<<1, 128>>>();
    k_prep_w<<<16, 256>>>(lw);
    k_csr_zero<<<79, 256>>>();
    k_csr_count<<<1250, 256>>>(ei);
    k_csr_scan<<<1, 1024>>>();
    k_csr_fill<<<1250, 256>>>(ei);
    k_init<<<2500, 256>>>(bnd, x);

    for (int it = 0; it < NITER; ++it) {
        k_tr<<<1, 128>>>(trw, trb);
        k_soft<<<148, 512, 131072>>>(ri, it);
        k_pick<<<1, 1024>>>(0);
        k_hist1<<<148, 512, 131072>>>(0);
        k_pick<<<1, 1024>>>(1);
        k_collect<<<1250, 256>>>();
        k_resolve<<<1, 1024>>>();
        k_scatter<<<2500, 256>>>(x, ei, ri);
        k_epi<<<2500, 128>>>(x, lb, lng, lnb, it);
    }
}